// round 11
// baseline (speedup 1.0000x reference)
#include <cuda_runtime.h>

#define DIM 8
typedef unsigned int u32;
typedef unsigned long long u64;

#define TILE_ROWS 256
#define TILE_BYTES (TILE_ROWS * 32)
#define S_IN 4
#define S_OUT 3
#define NTHREADS 256
#define SMEM_BYTES ((S_IN + S_OUT) * TILE_BYTES + 64)

// ---------------- PTX helpers ----------------
__device__ __forceinline__ u32 s2u(const void* p) {
    u32 a;
    asm("{ .reg .u64 t; cvta.to.shared.u64 t, %1; cvt.u32.u64 %0, t; }"
        : "=r"(a) : "l"(p));
    return a;
}
__device__ __forceinline__ u64 pk2(float lo, float hi) {
    u64 r; asm("mov.b64 %0,{%1,%2};" : "=l"(r) : "f"(lo), "f"(hi)); return r;
}
__device__ __forceinline__ void upk2(u64 v, float& lo, float& hi) {
    asm("mov.b64 {%0,%1},%2;" : "=f"(lo), "=f"(hi) : "l"(v));
}
__device__ __forceinline__ u64 add2(u64 a, u64 b) {
    u64 r; asm("add.rn.f32x2 %0,%1,%2;" : "=l"(r) : "l"(a), "l"(b)); return r;
}

#define MBAR_INIT(a, c) \
    asm volatile("mbarrier.init.shared.b64 [%0], %1;" :: "r"(a), "r"(c) : "memory")
#define MBAR_EXPECT_TX(a, b) \
    asm volatile("mbarrier.arrive.expect_tx.shared.b64 _, [%0], %1;" :: "r"(a), "r"(b) : "memory")

#define MBAR_WAIT(mbar, parity) do {                                          \
    u32 _m = (mbar), _p = (parity), _done;                                    \
    asm volatile("{\n\t.reg .pred p;\n\t"                                     \
        "mbarrier.try_wait.parity.acquire.cta.shared::cta.b64 p, [%1], %2;\n\t" \
        "selp.b32 %0, 1, 0, p;\n\t}"                                          \
        : "=r"(_done) : "r"(_m), "r"(_p) : "memory");                         \
    if (!_done) {                                                             \
        asm volatile("{\n\t.reg .pred P1;\n\t"                                \
            "W_%=:\n\t"                                                       \
            "mbarrier.try_wait.parity.acquire.cta.shared::cta.b64 P1, [%0], %1, 0x989680;\n\t" \
            "@P1 bra.uni D_%=;\n\t"                                           \
            "bra.uni W_%=;\n\t"                                               \
            "D_%=:\n\t}" :: "r"(_m), "r"(_p) : "memory");                     \
    }                                                                         \
} while (0)

__device__ __forceinline__ void bulk_load(u32 smem, const char* gmem, u32 bytes, u32 mbar) {
    asm volatile(
        "cp.async.bulk.shared::cta.global.mbarrier::complete_tx::bytes [%0], [%1], %2, [%3];"
        :: "r"(smem), "l"(gmem), "r"(bytes), "r"(mbar) : "memory");
}
__device__ __forceinline__ void bulk_store(char* gmem, u32 smem, u32 bytes) {
    asm volatile("cp.async.bulk.global.shared::cta.bulk_group [%0], [%1], %2;"
                 :: "l"(gmem), "r"(smem), "r"(bytes) : "memory");
}
#define BULK_COMMIT() asm volatile("cp.async.bulk.commit_group;" ::: "memory")
#define BULK_WAIT_READ(n) asm volatile("cp.async.bulk.wait_group.read %0;" :: "n"(n) : "memory")
#define BULK_WAIT_ALL() asm volatile("cp.async.bulk.wait_group 0;" ::: "memory")
#define FENCE_ASYNC() asm volatile("fence.proxy.async.shared::cta;" ::: "memory")

__device__ __forceinline__ void lds128(u32 a, float v[4]) {
    asm("ld.shared.v4.f32 {%0,%1,%2,%3},[%4];"
        : "=f"(v[0]), "=f"(v[1]), "=f"(v[2]), "=f"(v[3]) : "r"(a));
}
__device__ __forceinline__ void sts128(u32 a, const float v[4]) {
    asm volatile("st.shared.v4.f32 [%0],{%1,%2,%3,%4};"
                 :: "r"(a), "f"(v[0]), "f"(v[1]), "f"(v[2]), "f"(v[3]) : "memory");
}

// ---------------- E8 row decode (validated: rel_err 0.0 across 6 runs) ----------------
__device__ __forceinline__ void e8_row(const float x[DIM], float r[DIM]) {
    const u64 MAG2  = 0x4B4000004B400000ull;  // {12582912, 12582912}
    const u64 NMAG2 = 0xCB400000CB400000ull;

    float t[DIM], f[DIM], d[DIM];
#pragma unroll
    for (int p = 0; p < 4; ++p) {
        u64 xp = pk2(x[2 * p], x[2 * p + 1]);
        u64 tp = add2(xp, MAG2);     // mantissa LSB = parity(round(x))
        u64 fp = add2(tp, NMAG2);    // f = round-half-even(x), exact
        upk2(tp, t[2 * p], t[2 * p + 1]);
        upk2(fp, f[2 * p], f[2 * p + 1]);
    }
#pragma unroll
    for (int i = 0; i < DIM; ++i) d[i] = x[i] - f[i];  // exact residual

    u32 tb[DIM], db[DIM];
#pragma unroll
    for (int i = 0; i < DIM; ++i) {
        tb[i] = __float_as_uint(t[i]);
        db[i] = __float_as_uint(d[i]);
    }

    float amax = fabsf(d[0]), amin = amax;
    int imax = 0, imin = 0;
#pragma unroll
    for (int i = 1; i < DIM; ++i) {
        float ad = fabsf(d[i]);
        imax = (ad > amax) ? i : imax;  amax = fmaxf(amax, ad);
        imin = (ad < amin) ? i : imin;  amin = fminf(amin, ad);
    }

    u32 T  = (tb[0] ^ tb[1]) ^ (tb[2] ^ tb[3]) ^ ((tb[4] ^ tb[5]) ^ (tb[6] ^ tb[7]));
    u32 SG = (db[0] ^ db[1]) ^ (db[2] ^ db[3]) ^ ((db[4] ^ db[5]) ^ (db[6] ^ db[7]));
    const bool odd0 = (T & 1u) != 0u;
    const bool odd1 = ((T ^ (SG >> 31)) & 1u) != 0u;

    float Asum = ((fabsf(d[0]) + fabsf(d[1])) + (fabsf(d[2]) + fabsf(d[3]))) +
                 ((fabsf(d[4]) + fabsf(d[5])) + (fabsf(d[6]) + fabsf(d[7])));

    float s0 = odd0 ? __fmaf_rn(-2.0f, amax, 1.0f) : 0.0f;
    float s1 = odd1 ? (amin + amin) : 0.0f;
    float Dd = ((2.0f - Asum) + s1) - s0;

    if ((amin < 2e-6f) || (amin == 0.5f) || (fabsf(Dd) < 1e-5f)) {
        // Bit-exact reference recompute (rare: ~1e-4 of rows).
        float c0[DIM];
#pragma unroll
        for (int i = 0; i < DIM; ++i) {
            float step = (d[i] >= 0.0f) ? 1.0f : -1.0f;
            c0[i] = f[i] + ((odd0 && i == imax) ? step : 0.0f);
        }
        float y[DIM], f1[DIM], d1[DIM];
        int isum1 = 0;
#pragma unroll
        for (int i = 0; i < DIM; ++i) {
            y[i]  = x[i] - 0.5f;
            f1[i] = rintf(y[i]);
            d1[i] = y[i] - f1[i];
            isum1 += __float2int_rn(f1[i]);
        }
        int w1 = 0;
        float b1 = fabsf(d1[0]);
#pragma unroll
        for (int i = 1; i < DIM; ++i) {
            float ad = fabsf(d1[i]);
            if (ad > b1) { b1 = ad; w1 = i; }
        }
        const bool o1 = (isum1 & 1) != 0;
        float c1[DIM];
#pragma unroll
        for (int i = 0; i < DIM; ++i) {
            float step = (d1[i] >= 0.0f) ? 1.0f : -1.0f;
            c1[i] = (f1[i] + ((o1 && i == w1) ? step : 0.0f)) + 0.5f;
        }
        float s0q = 0.0f, s1q = 0.0f;
#pragma unroll
        for (int i = 0; i < DIM; ++i) {
            float e0 = x[i] - c0[i];
            float e1 = x[i] - c1[i];
            s0q = __fmaf_rn(e0, e0, s0q);
            s1q = __fmaf_rn(e1, e1, s1q);
        }
        const bool tk0 = (s0q <= s1q);
#pragma unroll
        for (int i = 0; i < DIM; ++i) r[i] = tk0 ? c0[i] : c1[i];
    } else {
        const bool take0 = (Dd >= 0.0f);
        int wsel = take0 ? (odd0 ? imax : 8) : (odd1 ? imin : 8);
        float kb = take0 ? 0.0f : 1.0f;
        float kf = take0 ? 2.0f : -1.0f;
#pragma unroll
        for (int i = 0; i < DIM; ++i) {
            float cs  = __uint_as_float((db[i] & 0x80000000u) | 0x3F000000u);
            float kap = (i == wsel) ? kf : kb;
            r[i] = __fmaf_rn(cs, kap, f[i]);
        }
    }
}

// ---------------- bulk-async staged streaming kernel ----------------
__global__ void __launch_bounds__(NTHREADS)
e8_closest_kernel(const char* __restrict__ xin, char* __restrict__ outv, int n_rows) {
    extern __shared__ char smem[];
    const u32 sbase = s2u(smem);
    const u32 in_base  = sbase;
    const u32 out_base = sbase + S_IN * TILE_BYTES;
    const u32 mbar     = sbase + (S_IN + S_OUT) * TILE_BYTES;

    const u32 tid = threadIdx.x;
    const u32 G = gridDim.x;
    const u32 c = blockIdx.x;
    const u32 n_tiles = ((u32)n_rows + TILE_ROWS - 1) / TILE_ROWS;

    if (tid == 0) {
#pragma unroll
        for (int s = 0; s < S_IN; ++s) MBAR_INIT(mbar + 8 * s, 1);
    }
    __syncthreads();

    // Prologue: prefetch up to S_IN tiles
    if (tid == 0) {
#pragma unroll
        for (u32 k = 0; k < S_IN; ++k) {
            u32 tile = c + k * G;
            if (tile < n_tiles) {
                u32 rows = min((u32)TILE_ROWS, (u32)n_rows - tile * TILE_ROWS);
                u32 bytes = rows * 32u;
                MBAR_EXPECT_TX(mbar + 8 * k, bytes);
                bulk_load(in_base + k * TILE_BYTES, xin + (size_t)tile * TILE_BYTES,
                          bytes, mbar + 8 * k);
            }
        }
    }

    for (u32 j = 0;; ++j) {
        u32 tile = c + j * G;
        if (tile >= n_tiles) break;
        const u32 si = j % S_IN;
        const u32 so = j % S_OUT;
        const u32 phase = (j / S_IN) & 1u;
        const u32 rows = min((u32)TILE_ROWS, (u32)n_rows - tile * TILE_ROWS);

        // load of this tile complete?
        MBAR_WAIT(mbar + 8 * si, phase);
        // out buffer so reused from iteration j-S_OUT: drain its bulk-store read
        if (tid == 0 && j >= S_OUT) BULK_WAIT_READ(S_OUT - 1);
        __syncthreads();

        if (tid < rows) {
            u32 ra = in_base + si * TILE_BYTES + tid * 32u;
            float x[DIM], r[DIM];
            lds128(ra,       x);
            lds128(ra + 16u, x + 4);
            e8_row(x, r);
            u32 wa = out_base + so * TILE_BYTES + tid * 32u;
            sts128(wa,       r);
            sts128(wa + 16u, r + 4);
        }
        __syncthreads();

        if (tid == 0) {
            FENCE_ASYNC();
            bulk_store(outv + (size_t)tile * TILE_BYTES,
                       out_base + so * TILE_BYTES, rows * 32u);
            BULK_COMMIT();
            // prefetch tile j+S_IN into the buffer just consumed
            u32 nt = tile + S_IN * G;
            if (nt < n_tiles) {
                u32 nrows = min((u32)TILE_ROWS, (u32)n_rows - nt * TILE_ROWS);
                u32 nbytes = nrows * 32u;
                MBAR_EXPECT_TX(mbar + 8 * si, nbytes);
                bulk_load(in_base + si * TILE_BYTES, xin + (size_t)nt * TILE_BYTES,
                          nbytes, mbar + 8 * si);
            }
        }
    }

    if (tid == 0) BULK_WAIT_ALL();
}

extern "C" void kernel_launch(void* const* d_in, const int* in_sizes, int n_in,
                              void* d_out, int out_size) {
    const char* x = (const char*)d_in[0];
    char* out = (char*)d_out;
    const int n_rows = in_sizes[0] / DIM;
    const u32 n_tiles = ((u32)n_rows + TILE_ROWS - 1) / TILE_ROWS;

    static bool attr_set = false;
    if (!attr_set) {
        cudaFuncSetAttribute(e8_closest_kernel,
                             cudaFuncAttributeMaxDynamicSharedMemorySize, SMEM_BYTES);
        attr_set = true;
    }

    u32 grid = 456;  // 152 SMs x 3 CTAs
    if (grid > n_tiles) grid = n_tiles;
    e8_closest_kernel<<<grid, NTHREADS, SMEM_BYTES>>>(x, out, n_rows);
}

// round 12
// speedup vs baseline: 1.1205x; 1.1205x over previous
#include <cuda_runtime.h>

#define DIM 8
typedef unsigned int u32;
typedef unsigned long long u64;

// packed f32x2 helpers (sm_103a)
__device__ __forceinline__ u64 pk2(float lo, float hi) {
    u64 r; asm("mov.b64 %0,{%1,%2};" : "=l"(r) : "f"(lo), "f"(hi)); return r;
}
__device__ __forceinline__ void upk2(u64 v, float& lo, float& hi) {
    asm("mov.b64 {%0,%1},%2;" : "=f"(lo), "=f"(hi) : "l"(v));
}
__device__ __forceinline__ u64 add2(u64 a, u64 b) {
    u64 r; asm("add.rn.f32x2 %0,%1,%2;" : "=l"(r) : "l"(a), "l"(b)); return r;
}

// 256-bit global load (read-only path) / store (evict-first)
__device__ __forceinline__ void ldg256(const float* p, float v[8]) {
    u32 a0, a1, a2, a3, a4, a5, a6, a7;
    asm("ld.global.nc.v8.b32 {%0,%1,%2,%3,%4,%5,%6,%7},[%8];"
        : "=r"(a0), "=r"(a1), "=r"(a2), "=r"(a3),
          "=r"(a4), "=r"(a5), "=r"(a6), "=r"(a7)
        : "l"(p));
    v[0] = __uint_as_float(a0); v[1] = __uint_as_float(a1);
    v[2] = __uint_as_float(a2); v[3] = __uint_as_float(a3);
    v[4] = __uint_as_float(a4); v[5] = __uint_as_float(a5);
    v[6] = __uint_as_float(a6); v[7] = __uint_as_float(a7);
}
__device__ __forceinline__ void stg256_cs(float* p, const float v[8]) {
    asm("st.global.cs.v8.b32 [%0],{%1,%2,%3,%4,%5,%6,%7,%8};"
        :: "l"(p),
           "r"(__float_as_uint(v[0])), "r"(__float_as_uint(v[1])),
           "r"(__float_as_uint(v[2])), "r"(__float_as_uint(v[3])),
           "r"(__float_as_uint(v[4])), "r"(__float_as_uint(v[5])),
           "r"(__float_as_uint(v[6])), "r"(__float_as_uint(v[7])));
}

// One E8 row decode: hot analytic path + inline bit-exact fallback.
__device__ __forceinline__ void e8_row(const float x[DIM], float r[DIM]) {
    const u64 MAG2  = 0x4B4000004B400000ull;  // {12582912, 12582912}
    const u64 NMAG2 = 0xCB400000CB400000ull;

    float t[DIM], f[DIM], d[DIM];
#pragma unroll
    for (int p = 0; p < 4; ++p) {
        u64 xp = pk2(x[2 * p], x[2 * p + 1]);
        u64 tp = add2(xp, MAG2);     // mantissa LSB = parity(round(x))
        u64 fp = add2(tp, NMAG2);    // f = round-half-even(x), exact
        upk2(tp, t[2 * p], t[2 * p + 1]);
        upk2(fp, f[2 * p], f[2 * p + 1]);
    }
#pragma unroll
    for (int i = 0; i < DIM; ++i) d[i] = x[i] - f[i];  // exact residual

    u32 tb[DIM], db[DIM];
#pragma unroll
    for (int i = 0; i < DIM; ++i) {
        tb[i] = __float_as_uint(t[i]);
        db[i] = __float_as_uint(d[i]);
    }

    float amax = fabsf(d[0]), amin = amax;
    int imax = 0, imin = 0;
#pragma unroll
    for (int i = 1; i < DIM; ++i) {
        float ad = fabsf(d[i]);
        imax = (ad > amax) ? i : imax;  amax = fmaxf(amax, ad);
        imin = (ad < amin) ? i : imin;  amin = fminf(amin, ad);
    }

    u32 T  = (tb[0] ^ tb[1]) ^ (tb[2] ^ tb[3]) ^ ((tb[4] ^ tb[5]) ^ (tb[6] ^ tb[7]));
    u32 SG = (db[0] ^ db[1]) ^ (db[2] ^ db[3]) ^ ((db[4] ^ db[5]) ^ (db[6] ^ db[7]));
    const bool odd0 = (T & 1u) != 0u;
    const bool odd1 = ((T ^ (SG >> 31)) & 1u) != 0u;

    float Asum = ((fabsf(d[0]) + fabsf(d[1])) + (fabsf(d[2]) + fabsf(d[3]))) +
                 ((fabsf(d[4]) + fabsf(d[5])) + (fabsf(d[6]) + fabsf(d[7])));

    // dist1 - dist0 = 2 - sum|d| + odd1*2*min|d| - odd0*(1 - 2*max|d|)
    float s0 = odd0 ? __fmaf_rn(-2.0f, amax, 1.0f) : 0.0f;
    float s1 = odd1 ? (amin + amin) : 0.0f;
    float Dd = ((2.0f - Asum) + s1) - s0;

    if ((amin < 2e-6f) || (amin == 0.5f) || (fabsf(Dd) < 1e-5f)) {
        // Bit-exact reference recompute (rare: ~1e-4 of rows).
        float c0[DIM];
#pragma unroll
        for (int i = 0; i < DIM; ++i) {
            float step = (d[i] >= 0.0f) ? 1.0f : -1.0f;
            c0[i] = f[i] + ((odd0 && i == imax) ? step : 0.0f);
        }
        float y[DIM], f1[DIM], d1[DIM];
        int isum1 = 0;
#pragma unroll
        for (int i = 0; i < DIM; ++i) {
            y[i]  = x[i] - 0.5f;
            f1[i] = rintf(y[i]);
            d1[i] = y[i] - f1[i];
            isum1 += __float2int_rn(f1[i]);
        }
        int w1 = 0;
        float b1 = fabsf(d1[0]);
#pragma unroll
        for (int i = 1; i < DIM; ++i) {
            float ad = fabsf(d1[i]);
            if (ad > b1) { b1 = ad; w1 = i; }
        }
        const bool o1 = (isum1 & 1) != 0;
        float c1[DIM];
#pragma unroll
        for (int i = 0; i < DIM; ++i) {
            float step = (d1[i] >= 0.0f) ? 1.0f : -1.0f;
            c1[i] = (f1[i] + ((o1 && i == w1) ? step : 0.0f)) + 0.5f;
        }
        float s0q = 0.0f, s1q = 0.0f;
#pragma unroll
        for (int i = 0; i < DIM; ++i) {
            float e0 = x[i] - c0[i];
            float e1 = x[i] - c1[i];
            s0q = __fmaf_rn(e0, e0, s0q);
            s1q = __fmaf_rn(e1, e1, s1q);
        }
        const bool tk0 = (s0q <= s1q);
#pragma unroll
        for (int i = 0; i < DIM; ++i) r[i] = tk0 ? c0[i] : c1[i];
    } else {
        const bool take0 = (Dd >= 0.0f);
        int wsel = take0 ? (odd0 ? imax : 8) : (odd1 ? imin : 8);
        float kb = take0 ? 0.0f : 1.0f;
        float kf = take0 ? 2.0f : -1.0f;
#pragma unroll
        for (int i = 0; i < DIM; ++i) {
            float cs  = __uint_as_float((db[i] & 0x80000000u) | 0x3F000000u);
            float kap = (i == wsel) ? kf : kb;
            r[i] = __fmaf_rn(cs, kap, f[i]);
        }
    }
}

// 3 rows per thread, 3 front-batched LDG.256 (6 KB contiguous per warp batch),
// evict-first 256-bit stores, stores interleaved per row.
__global__ void __launch_bounds__(256)
e8_closest_kernel(const float* __restrict__ xin, float* __restrict__ outv, int n_rows) {
    u32 tid = blockIdx.x * blockDim.x + threadIdx.x;
    u32 base = 3u * tid;
    if (base >= (u32)n_rows) return;

    if (base + 2u < (u32)n_rows) {
        float x0[DIM], x1[DIM], x2[DIM];
        const float* p = xin + (size_t)base * DIM;
        ldg256(p,           x0);
        ldg256(p + DIM,     x1);
        ldg256(p + 2 * DIM, x2);

        float* q = outv + (size_t)base * DIM;
        float r[DIM];
        e8_row(x0, r); stg256_cs(q,           r);
        e8_row(x1, r); stg256_cs(q + DIM,     r);
        e8_row(x2, r); stg256_cs(q + 2 * DIM, r);
    } else {
        // guarded tail (last thread when n_rows % 3 != 0)
#pragma unroll
        for (u32 k = 0; k < 3; ++k) {
            u32 row = base + k;
            if (row >= (u32)n_rows) break;
            float x[DIM], r[DIM];
            ldg256(xin + (size_t)row * DIM, x);
            e8_row(x, r);
            stg256_cs(outv + (size_t)row * DIM, r);
        }
    }
}

extern "C" void kernel_launch(void* const* d_in, const int* in_sizes, int n_in,
                              void* d_out, int out_size) {
    const float* x = (const float*)d_in[0];
    float* out = (float*)d_out;
    const int n_rows = in_sizes[0] / DIM;
    const int threads = 256;
    const int rows_per_block = threads * 3;
    const int blocks = (n_rows + rows_per_block - 1) / rows_per_block;
    e8_closest_kernel<<<blocks, threads>>>(x, out, n_rows);
}